// round 3
// baseline (speedup 1.0000x reference)
#include <cuda_runtime.h>

// Problem dims (fixed)
#define T_DIM 100
#define B_DIM 128
#define F_DIM 4096
#define C_DIM 10

#define ROWS_PER_BLOCK 4          // consecutive (t,b) rows per block (128 % 4 == 0 -> same t)
#define THREADS_K1 128
#define F4_DIM (F_DIM / 4)        // 1024 float4 (= ulonglong2) per row
#define ITERS (F4_DIM / THREADS_K1)  // 8
#define BC (B_DIM * C_DIM)        // 1280

typedef unsigned long long u64;

// Packed f32x2 ops (sm_100a+): one instruction, two fp32 lanes.
__device__ __forceinline__ u64 mul2(u64 a, u64 b) {
    u64 d; asm("mul.rn.f32x2 %0, %1, %2;" : "=l"(d) : "l"(a), "l"(b)); return d;
}
__device__ __forceinline__ u64 fma2(u64 a, u64 b, u64 c) {
    u64 d; asm("fma.rn.f32x2 %0, %1, %2, %3;" : "=l"(d) : "l"(a), "l"(b), "l"(c)); return d;
}
__device__ __forceinline__ float hsum2(u64 p) {
    float lo, hi; asm("mov.b64 {%0, %1}, %2;" : "=f"(lo), "=f"(hi) : "l"(p));
    return lo + hi;
}

// Scratch for current, TRANSPOSED: g_currentT[(b*C + c) * T + t]  (512 KB)
__device__ float g_currentT[BC * T_DIM];

// Kernel 1: current[t,b,c] = 2 * sum_f spike*mask*W[c,f] + bias[c]
__global__ __launch_bounds__(THREADS_K1)
void snn_gemv_kernel(const float* __restrict__ spike,
                     const float* __restrict__ mask,
                     const float* __restrict__ W,
                     const float* __restrict__ bias)
{
    const int row0 = blockIdx.x * ROWS_PER_BLOCK;
    const int tid  = threadIdx.x;

    // ulonglong2 = 16 bytes = 4 floats = 2 packed f32x2 pairs
    const ulonglong2* sp = reinterpret_cast<const ulonglong2*>(spike) + (size_t)row0 * F4_DIM;
    const ulonglong2* mk = reinterpret_cast<const ulonglong2*>(mask)  + (size_t)row0 * F4_DIM;
    const ulonglong2* W2 = reinterpret_cast<const ulonglong2*>(W);

    u64 acc[ROWS_PER_BLOCK][C_DIM];   // packed pair accumulators
#pragma unroll
    for (int r = 0; r < ROWS_PER_BLOCK; ++r)
#pragma unroll
        for (int c = 0; c < C_DIM; ++c)
            acc[r][c] = 0ull;

#pragma unroll
    for (int it = 0; it < ITERS; ++it) {
        const int f4 = tid + it * THREADS_K1;

        // x = spike * mask, packed. Streaming loads (evict-first) keep W in L1.
        u64 xlo[ROWS_PER_BLOCK], xhi[ROWS_PER_BLOCK];
#pragma unroll
        for (int r = 0; r < ROWS_PER_BLOCK; ++r) {
            const ulonglong2 s2 = __ldcs(&sp[(size_t)r * F4_DIM + f4]);
            const ulonglong2 m2 = __ldcs(&mk[(size_t)r * F4_DIM + f4]);
            xlo[r] = mul2(s2.x, m2.x);
            xhi[r] = mul2(s2.y, m2.y);
        }

#pragma unroll
        for (int c = 0; c < C_DIM; ++c) {
            const ulonglong2 wv = __ldg(&W2[(size_t)c * F4_DIM + f4]);
#pragma unroll
            for (int r = 0; r < ROWS_PER_BLOCK; ++r) {
                acc[r][c] = fma2(xlo[r], wv.x, acc[r][c]);
                acc[r][c] = fma2(xhi[r], wv.y, acc[r][c]);
            }
        }
    }

    // Reduce: horizontal pair-sum, warp shuffle, then cross-warp via smem.
    __shared__ float sred[THREADS_K1 / 32][ROWS_PER_BLOCK * C_DIM];
    const int lane = tid & 31;
    const int warp = tid >> 5;

#pragma unroll
    for (int r = 0; r < ROWS_PER_BLOCK; ++r) {
#pragma unroll
        for (int c = 0; c < C_DIM; ++c) {
            float v = hsum2(acc[r][c]);
#pragma unroll
            for (int o = 16; o > 0; o >>= 1)
                v += __shfl_down_sync(0xffffffffu, v, o);
            if (lane == 0)
                sred[warp][r * C_DIM + c] = v;
        }
    }
    __syncthreads();

    if (tid < ROWS_PER_BLOCK * C_DIM) {
        float s = sred[0][tid] + sred[1][tid] + sred[2][tid] + sred[3][tid];
        const int r = tid / C_DIM;
        const int c = tid % C_DIM;
        const int row = row0 + r;
        const int t = row / B_DIM;
        const int b = row % B_DIM;
        // 2.0f = 1/keep (dropout); bias added once. Transposed store.
        g_currentT[(size_t)(b * C_DIM + c) * T_DIM + t] = 2.0f * s + bias[c];
    }
}

// Kernel 2: LIF scan over T per (b,c). 32-thread blocks spread across 40 SMs.
__global__ __launch_bounds__(32)
void snn_scan_kernel(float* __restrict__ out)
{
    const int idx = blockIdx.x * 32 + threadIdx.x;  // 0..1279
    if (idx >= BC) return;

    const float4* cur4 = reinterpret_cast<const float4*>(g_currentT + (size_t)idx * T_DIM);

    float vals[T_DIM];
#pragma unroll
    for (int i = 0; i < T_DIM / 4; ++i) {
        const float4 c4 = cur4[i];
        vals[4 * i + 0] = c4.x;
        vals[4 * i + 1] = c4.y;
        vals[4 * i + 2] = c4.z;
        vals[4 * i + 3] = c4.w;
    }

    float v = 0.0f;
#pragma unroll
    for (int t = 0; t < T_DIM; ++t) {
        v = 0.9f * v + vals[t];
        const float s = (v - 1.0f) > 0.0f ? 1.0f : 0.0f;
        out[(size_t)t * BC + idx] = s;   // coalesced across threads
        v -= s;
    }
}

extern "C" void kernel_launch(void* const* d_in, const int* in_sizes, int n_in,
                              void* d_out, int out_size)
{
    const float* spike = (const float*)d_in[0];  // [T,B,F]
    const float* mask  = (const float*)d_in[1];  // [T,B,F]
    const float* W     = (const float*)d_in[2];  // [C,F]
    const float* bias  = (const float*)d_in[3];  // [C]
    float* out = (float*)d_out;                  // [T,B,C]

    const int grid1 = (T_DIM * B_DIM) / ROWS_PER_BLOCK;  // 3200

    snn_gemv_kernel<<<grid1, THREADS_K1>>>(spike, mask, W, bias);

    snn_scan_kernel<<<BC / 32, 32>>>(out);               // 40 blocks x 32 thr
}

// round 4
// speedup vs baseline: 1.1424x; 1.1424x over previous
#include <cuda_runtime.h>

// Problem dims (fixed)
#define T_DIM 100
#define B_DIM 128
#define F_DIM 4096
#define C_DIM 10

#define ROWS_PER_BLOCK 8          // consecutive (t,b) rows per block (same t)
#define RPAIRS (ROWS_PER_BLOCK / 2)
#define THREADS_K1 128
#define F4_DIM (F_DIM / 4)        // 1024 float4 per row
#define ITERS (F4_DIM / THREADS_K1)  // 8
#define BC (B_DIM * C_DIM)        // 1280

typedef unsigned long long u64;

// Packed f32x2 ops (Blackwell): one fma-pipe instruction, two fp32 lanes.
__device__ __forceinline__ u64 mul2(u64 a, u64 b) {
    u64 d; asm("mul.rn.f32x2 %0, %1, %2;" : "=l"(d) : "l"(a), "l"(b)); return d;
}
__device__ __forceinline__ u64 fma2(u64 a, u64 b, u64 c) {
    u64 d; asm("fma.rn.f32x2 %0, %1, %2, %3;" : "=l"(d) : "l"(a), "l"(b), "l"(c)); return d;
}
__device__ __forceinline__ u64 pack2(float lo, float hi) {
    u64 d; asm("mov.b64 %0, {%1, %2};" : "=l"(d) : "f"(lo), "f"(hi)); return d;
}
__device__ __forceinline__ void unpack2(u64 p, float& lo, float& hi) {
    asm("mov.b64 {%0, %1}, %2;" : "=f"(lo), "=f"(hi) : "l"(p));
}

// Scratch for current, TRANSPOSED: g_currentT[(b*C + c) * T + t]  (512 KB)
__device__ float g_currentT[BC * T_DIM];

// Kernel 1: current[t,b,c] = 2 * sum_f spike*mask*W[c,f] + bias[c]
// Row-paired f32x2: each fma2 accumulates the same (c,f) term for TWO rows.
__global__ __launch_bounds__(THREADS_K1)
void snn_gemv_kernel(const float* __restrict__ spike,
                     const float* __restrict__ mask,
                     const float* __restrict__ W,
                     const float* __restrict__ bias)
{
    const int row0 = blockIdx.x * ROWS_PER_BLOCK;
    const int tid  = threadIdx.x;

    const float4* sp = reinterpret_cast<const float4*>(spike) + (size_t)row0 * F4_DIM;
    const float4* mk = reinterpret_cast<const float4*>(mask)  + (size_t)row0 * F4_DIM;
    const float4* W4 = reinterpret_cast<const float4*>(W);

    // acc2[rp][c]: lo lane = row 2*rp, hi lane = row 2*rp+1
    u64 acc2[RPAIRS][C_DIM];
#pragma unroll
    for (int rp = 0; rp < RPAIRS; ++rp)
#pragma unroll
        for (int c = 0; c < C_DIM; ++c)
            acc2[rp][c] = 0ull;

#pragma unroll
    for (int it = 0; it < ITERS; ++it) {
        const int f4 = tid + it * THREADS_K1;

        // Stream in 8 rows of spike+mask (evict-first so W stays L1-resident).
        float4 s4[ROWS_PER_BLOCK], m4[ROWS_PER_BLOCK];
#pragma unroll
        for (int r = 0; r < ROWS_PER_BLOCK; ++r) {
            s4[r] = __ldcs(&sp[(size_t)r * F4_DIM + f4]);
            m4[r] = __ldcs(&mk[(size_t)r * F4_DIM + f4]);
        }

        // x pairs: x[rp][fi] = { s*m (row 2rp), s*m (row 2rp+1) } at f-elem fi
        u64 x[RPAIRS][4];
#pragma unroll
        for (int rp = 0; rp < RPAIRS; ++rp) {
            const float4 sa = s4[2 * rp], sb = s4[2 * rp + 1];
            const float4 ma = m4[2 * rp], mb = m4[2 * rp + 1];
            x[rp][0] = mul2(pack2(sa.x, sb.x), pack2(ma.x, mb.x));
            x[rp][1] = mul2(pack2(sa.y, sb.y), pack2(ma.y, mb.y));
            x[rp][2] = mul2(pack2(sa.z, sb.z), pack2(ma.z, mb.z));
            x[rp][3] = mul2(pack2(sa.w, sb.w), pack2(ma.w, mb.w));
        }

        // 10 W loads per iter amortized across 8 rows; duplicate each scalar
        // into both lanes (alu-pipe MOVs, overlap with fma pipe).
#pragma unroll
        for (int c = 0; c < C_DIM; ++c) {
            const float4 wv = __ldg(&W4[(size_t)c * F4_DIM + f4]);
            const u64 w0 = pack2(wv.x, wv.x);
            const u64 w1 = pack2(wv.y, wv.y);
            const u64 w2 = pack2(wv.z, wv.z);
            const u64 w3 = pack2(wv.w, wv.w);
#pragma unroll
            for (int rp = 0; rp < RPAIRS; ++rp) {
                u64 a = acc2[rp][c];
                a = fma2(x[rp][0], w0, a);
                a = fma2(x[rp][1], w1, a);
                a = fma2(x[rp][2], w2, a);
                a = fma2(x[rp][3], w3, a);
                acc2[rp][c] = a;
            }
        }
    }

    // Reduce: unpack pairs to per-row scalars, warp shuffle, cross-warp smem.
    __shared__ float sred[THREADS_K1 / 32][ROWS_PER_BLOCK * C_DIM];
    const int lane = tid & 31;
    const int warp = tid >> 5;

#pragma unroll
    for (int rp = 0; rp < RPAIRS; ++rp) {
#pragma unroll
        for (int c = 0; c < C_DIM; ++c) {
            float vlo, vhi;
            unpack2(acc2[rp][c], vlo, vhi);
#pragma unroll
            for (int o = 16; o > 0; o >>= 1) {
                vlo += __shfl_down_sync(0xffffffffu, vlo, o);
                vhi += __shfl_down_sync(0xffffffffu, vhi, o);
            }
            if (lane == 0) {
                sred[warp][(2 * rp) * C_DIM + c]     = vlo;
                sred[warp][(2 * rp + 1) * C_DIM + c] = vhi;
            }
        }
    }
    __syncthreads();

    if (tid < ROWS_PER_BLOCK * C_DIM) {
        float s = sred[0][tid] + sred[1][tid] + sred[2][tid] + sred[3][tid];
        const int r = tid / C_DIM;
        const int c = tid % C_DIM;
        const int row = row0 + r;
        const int t = row / B_DIM;
        const int b = row % B_DIM;
        // 2.0f = 1/keep (dropout); bias added once. Transposed store.
        g_currentT[(size_t)(b * C_DIM + c) * T_DIM + t] = 2.0f * s + bias[c];
    }
}

// Kernel 2: LIF scan over T per (b,c). 40 blocks x 32 threads.
__global__ __launch_bounds__(32)
void snn_scan_kernel(float* __restrict__ out)
{
    const int idx = blockIdx.x * 32 + threadIdx.x;  // 0..1279
    if (idx >= BC) return;

    const float4* cur4 = reinterpret_cast<const float4*>(g_currentT + (size_t)idx * T_DIM);

    float vals[T_DIM];
#pragma unroll
    for (int i = 0; i < T_DIM / 4; ++i) {
        const float4 c4 = cur4[i];
        vals[4 * i + 0] = c4.x;
        vals[4 * i + 1] = c4.y;
        vals[4 * i + 2] = c4.z;
        vals[4 * i + 3] = c4.w;
    }

    float v = 0.0f;
#pragma unroll
    for (int t = 0; t < T_DIM; ++t) {
        v = 0.9f * v + vals[t];
        const float s = (v - 1.0f) > 0.0f ? 1.0f : 0.0f;
        out[(size_t)t * BC + idx] = s;   // coalesced across threads
        v -= s;
    }
}

extern "C" void kernel_launch(void* const* d_in, const int* in_sizes, int n_in,
                              void* d_out, int out_size)
{
    const float* spike = (const float*)d_in[0];  // [T,B,F]
    const float* mask  = (const float*)d_in[1];  // [T,B,F]
    const float* W     = (const float*)d_in[2];  // [C,F]
    const float* bias  = (const float*)d_in[3];  // [C]
    float* out = (float*)d_out;                  // [T,B,C]

    const int grid1 = (T_DIM * B_DIM) / ROWS_PER_BLOCK;  // 1600

    snn_gemv_kernel<<<grid1, THREADS_K1>>>(spike, mask, W, bias);

    snn_scan_kernel<<<BC / 32, 32>>>(out);               // 40 blocks x 32 thr
}